// round 10
// baseline (speedup 1.0000x reference)
#include <cuda_runtime.h>
#include <math.h>
#include <cstdint>

#define T_TOK   16384
#define DIM     2048
#define N_EXP   64
#define NC      128
#define TOPK    8

#define CTA_M   128
#define CTA_N   64
#define KT      32
#define NTILE   (DIM / KT)      // 64
#define APAD    36
#define BPAD    36
#define ABUF    (CTA_M * APAD)  // floats, one stage
#define BBUF    (CTA_N * BPAD)
// smem: Araw[2] + Bhi[2] + Blo[2] + acc2[32][256]
#define SM_FLOATS (2 * ABUF + 4 * BBUF + 32 * 256)
#define DYN_SMEM  (SM_FLOATS * 4)   // 106496 B -> 2 CTAs/SM

__device__ float g_logits[(size_t)T_TOK * NC];
__device__ float g_Whi[(size_t)NC * DIM];
__device__ float g_Wlo[(size_t)NC * DIM];

__device__ __forceinline__ float f2tf(float x) {
    uint32_t r;
    asm("cvt.rna.tf32.f32 %0, %1;" : "=r"(r) : "f"(x));
    return __uint_as_float(r);
}
__device__ __forceinline__ void mma8(float c[4], const uint32_t a[4], const uint32_t b[2]) {
    asm volatile(
        "mma.sync.aligned.m16n8k8.row.col.f32.tf32.tf32.f32 "
        "{%0,%1,%2,%3}, {%4,%5,%6,%7}, {%8,%9}, {%0,%1,%2,%3};"
        : "+f"(c[0]), "+f"(c[1]), "+f"(c[2]), "+f"(c[3])
        : "r"(a[0]), "r"(a[1]), "r"(a[2]), "r"(a[3]), "r"(b[0]), "r"(b[1]));
}
__device__ __forceinline__ uint32_t smem_u32(const void* p) {
    uint32_t a;
    asm("{ .reg .u64 t; cvta.to.shared.u64 t, %1; cvt.u32.u64 %0, t; }"
        : "=r"(a) : "l"(p));
    return a;
}
__device__ __forceinline__ void cp16(uint32_t dst, const void* src) {
    asm volatile("cp.async.ca.shared.global [%0], [%1], 16;"
                 :: "r"(dst), "l"(src) : "memory");
}
#define CP_COMMIT() asm volatile("cp.async.commit_group;" ::: "memory")
#define CP_WAIT0()  asm volatile("cp.async.wait_group 0;" ::: "memory")

// ---------------------------------------------------------------------------
// Kernel 0: split W = [Wg; Wn] into tf32 hi + lo
// ---------------------------------------------------------------------------
__global__ void wsplit_kernel(const float* __restrict__ Wg,
                              const float* __restrict__ Wn) {
    const int i0 = (blockIdx.x * 256 + threadIdx.x) * 16;
#pragma unroll
    for (int f = 0; f < 4; f++) {
        const int i = i0 + f * 4;
        float4 w = (i < N_EXP * DIM)
                 ? *(const float4*)(Wg + i)
                 : *(const float4*)(Wn + (i - N_EXP * DIM));
        float4 hi, lo;
        hi.x = f2tf(w.x); lo.x = f2tf(w.x - hi.x);
        hi.y = f2tf(w.y); lo.y = f2tf(w.y - hi.y);
        hi.z = f2tf(w.z); lo.z = f2tf(w.z - hi.z);
        hi.w = f2tf(w.w); lo.w = f2tf(w.w - hi.w);
        *(float4*)(g_Whi + i) = hi;
        *(float4*)(g_Wlo + i) = lo;
    }
}

// ---------------------------------------------------------------------------
// Kernel 1: 3xTF32 mma.sync GEMM. Numerics bitwise identical to R8 (same
// split, same MMA order, same 64k RN cascade). Scheduling: cp.async staging,
// acc2 in smem, 2 CTAs/SM.
// FIX vs R9: B loader now issues 2 cp16 per B array per thread (full 32-k
// coverage); R9 only wrote k=0..15 of Bhi/Blo — k=16..31 were garbage.
// ---------------------------------------------------------------------------
__global__ void __launch_bounds__(256, 2)
router_gemm_mma(const float* __restrict__ H) {
    extern __shared__ float sm[];
    float* Araw  = sm;                       // [2][CTA_M][APAD]
    float* Bhi   = sm + 2 * ABUF;            // [2][CTA_N][BPAD]
    float* Blo   = Bhi + 2 * BBUF;           // [2][CTA_N][BPAD]
    float* acc2s = Blo + 2 * BBUF;           // [32][256]

    const int tid  = threadIdx.x;
    const int lane = tid & 31;
    const int wid  = tid >> 5;
    const int wm   = wid & 3;
    const int wn   = wid >> 2;
    const int m0   = blockIdx.x * CTA_M;
    const int fr   = lane >> 2;
    const int fc   = lane & 3;

    // cp.async loader geometry
    const int a_r0 = tid >> 3, a_c4 = (tid & 7);        // A: 4 cp16/thread
    const int b_r  = tid >> 2, b_k8 = (tid & 3) * 8;    // B: 2 cp16/array/thread
    const float* aG  = H + (size_t)m0 * DIM;
    const float* bhG = g_Whi + (size_t)blockIdx.y * CTA_N * DIM;
    const float* blG = g_Wlo + (size_t)blockIdx.y * CTA_N * DIM;
    const uint32_t sA  = smem_u32(Araw);
    const uint32_t sBh = smem_u32(Bhi);
    const uint32_t sBl = smem_u32(Blo);

    float acc_a[2][4][4], acc_c[2][4][4];
#pragma unroll
    for (int i = 0; i < 2; i++)
#pragma unroll
        for (int j = 0; j < 4; j++)
#pragma unroll
            for (int r = 0; r < 4; r++) { acc_a[i][j][r] = 0.f; acc_c[i][j][r] = 0.f; }
#pragma unroll
    for (int r = 0; r < 32; r++) acc2s[r * 256 + tid] = 0.f;

    // issue stage for tile t into buffer b
    auto issue_tile = [&](int t, int b) {
#pragma unroll
        for (int f = 0; f < 4; f++) {
            const int row = a_r0 + f * 32;
            cp16(sA + (uint32_t)((b * ABUF + row * APAD + a_c4 * 4) * 4),
                 aG + (size_t)row * DIM + t * KT + a_c4 * 4);
        }
#pragma unroll
        for (int f = 0; f < 2; f++) {
            cp16(sBh + (uint32_t)((b * BBUF + b_r * BPAD + b_k8 + f * 4) * 4),
                 bhG + (size_t)b_r * DIM + t * KT + b_k8 + f * 4);
            cp16(sBl + (uint32_t)((b * BBUF + b_r * BPAD + b_k8 + f * 4) * 4),
                 blG + (size_t)b_r * DIM + t * KT + b_k8 + f * 4);
        }
        CP_COMMIT();
    };

    issue_tile(0, 0);
    CP_WAIT0();
    __syncthreads();

    for (int t = 0; t < NTILE; t++) {
        if (t + 1 < NTILE) issue_tile(t + 1, (t + 1) & 1);

        const float* Ab  = Araw + (t & 1) * ABUF;
        const float* Bhb = Bhi  + (t & 1) * BBUF;
        const float* Blb = Blo  + (t & 1) * BBUF;

#pragma unroll
        for (int ks = 0; ks < 4; ks++) {
            uint32_t ahi[2][4], alo[2][4];
#pragma unroll
            for (int mt = 0; mt < 2; mt++) {
                const float* ap = Ab + (wm * 32 + mt * 16 + fr) * APAD + ks * 8 + fc;
                float r0 = ap[0], r1 = ap[8 * APAD], r2 = ap[4], r3 = ap[8 * APAD + 4];
                float h0 = f2tf(r0), h1 = f2tf(r1), h2 = f2tf(r2), h3 = f2tf(r3);
                ahi[mt][0] = __float_as_uint(h0); alo[mt][0] = __float_as_uint(f2tf(r0 - h0));
                ahi[mt][1] = __float_as_uint(h1); alo[mt][1] = __float_as_uint(f2tf(r1 - h1));
                ahi[mt][2] = __float_as_uint(h2); alo[mt][2] = __float_as_uint(f2tf(r2 - h2));
                ahi[mt][3] = __float_as_uint(h3); alo[mt][3] = __float_as_uint(f2tf(r3 - h3));
            }
            uint32_t bhi[4][2], blo[4][2];
#pragma unroll
            for (int nt = 0; nt < 4; nt++) {
                const int bq = (wn * 32 + nt * 8 + fr) * BPAD + ks * 8 + fc;
                bhi[nt][0] = __float_as_uint(Bhb[bq]);
                bhi[nt][1] = __float_as_uint(Bhb[bq + 4]);
                blo[nt][0] = __float_as_uint(Blb[bq]);
                blo[nt][1] = __float_as_uint(Blb[bq + 4]);
            }
#pragma unroll
            for (int mt = 0; mt < 2; mt++)
#pragma unroll
                for (int nt = 0; nt < 4; nt++) mma8(acc_a[mt][nt], ahi[mt], bhi[nt]);
#pragma unroll
            for (int mt = 0; mt < 2; mt++)
#pragma unroll
                for (int nt = 0; nt < 4; nt++) mma8(acc_c[mt][nt], ahi[mt], blo[nt]);
#pragma unroll
            for (int mt = 0; mt < 2; mt++)
#pragma unroll
                for (int nt = 0; nt < 4; nt++) mma8(acc_c[mt][nt], alo[mt], bhi[nt]);
        }

        if ((t & 1) == 1) {   // 64k cascade (same expression/boundaries as R8)
#pragma unroll
            for (int mt = 0; mt < 2; mt++)
#pragma unroll
                for (int nt = 0; nt < 4; nt++)
#pragma unroll
                    for (int r = 0; r < 4; r++) {
                        const int idx = ((mt * 4 + nt) * 4 + r);
                        acc2s[idx * 256 + tid] += acc_a[mt][nt][r] + acc_c[mt][nt][r];
                        acc_a[mt][nt][r] = 0.f;
                        acc_c[mt][nt][r] = 0.f;
                    }
        }

        CP_WAIT0();
        __syncthreads();
    }

    // epilogue
#pragma unroll
    for (int mt = 0; mt < 2; mt++)
#pragma unroll
        for (int nt = 0; nt < 4; nt++) {
            const int row = m0 + wm * 32 + mt * 16 + fr;
            const int col = blockIdx.y * CTA_N + wn * 32 + nt * 8 + fc * 2;
            const int idx = (mt * 4 + nt) * 4;
            float v0 = acc2s[(idx + 0) * 256 + tid];
            float v1 = acc2s[(idx + 1) * 256 + tid];
            float v2 = acc2s[(idx + 2) * 256 + tid];
            float v3 = acc2s[(idx + 3) * 256 + tid];
            *(float2*)&g_logits[(size_t)row * NC + col]       = make_float2(v0, v1);
            *(float2*)&g_logits[(size_t)(row + 8) * NC + col] = make_float2(v2, v3);
        }
}

// ---------------------------------------------------------------------------
// Kernel 2: one warp per token — noisy logits, softmax(64), top-8 desc
// ---------------------------------------------------------------------------
__device__ __forceinline__ float softplus_f(float x) {
    return fmaxf(x, 0.0f) + log1pf(expf(-fabsf(x)));
}

__global__ void __launch_bounds__(256)
router_topk_kernel(const float* __restrict__ noise, float* __restrict__ out) {
    const int warp = (blockIdx.x * blockDim.x + threadIdx.x) >> 5;
    const int lane = threadIdx.x & 31;
    if (warp >= T_TOK) return;

    const float* row = g_logits + (size_t)warp * NC;
    const float* nz  = noise + (size_t)warp * N_EXP;

    float g0 = row[lane]      + nz[lane]      * softplus_f(row[64 + lane]);
    float g1 = row[lane + 32] + nz[lane + 32] * softplus_f(row[96 + lane]);

    float mx = fmaxf(g0, g1);
#pragma unroll
    for (int o = 16; o > 0; o >>= 1) mx = fmaxf(mx, __shfl_xor_sync(0xffffffffu, mx, o));
    float e0 = expf(g0 - mx), e1 = expf(g1 - mx);
    float s = e0 + e1;
#pragma unroll
    for (int o = 16; o > 0; o >>= 1) s += __shfl_xor_sync(0xffffffffu, s, o);
    const float inv = 1.0f / s;
    float p0 = e0 * inv, p1 = e1 * inv;

    float* gates = out + (size_t)2 * T_TOK * TOPK + (size_t)warp * N_EXP;
    gates[lane]      = p0;
    gates[lane + 32] = p1;

    float v0 = p0, v1 = p1;
    float* vals = out + (size_t)warp * TOPK;
    float* inds = out + (size_t)T_TOK * TOPK + (size_t)warp * TOPK;

#pragma unroll
    for (int r = 0; r < TOPK; r++) {
        float cv; int ci;
        if (v0 >= v1) { cv = v0; ci = lane; }
        else          { cv = v1; ci = lane + 32; }
#pragma unroll
        for (int o = 16; o > 0; o >>= 1) {
            float ov = __shfl_xor_sync(0xffffffffu, cv, o);
            int   oi = __shfl_xor_sync(0xffffffffu, ci, o);
            if (ov > cv || (ov == cv && oi < ci)) { cv = ov; ci = oi; }
        }
        if (lane == 0) { vals[r] = cv; inds[r] = (float)ci; }
        if (ci == lane)      v0 = -INFINITY;
        if (ci == lane + 32) v1 = -INFINITY;
    }
}

__global__ void dummy_kernel() {}

// ---------------------------------------------------------------------------
extern "C" void kernel_launch(void* const* d_in, const int* in_sizes, int n_in,
                              void* d_out, int out_size) {
    const float* H     = (const float*)d_in[0];
    const float* Wg    = (const float*)d_in[1];
    const float* Wn    = (const float*)d_in[2];
    const float* noise = (const float*)d_in[3];
    float* out = (float*)d_out;

    cudaFuncSetAttribute(router_gemm_mma,
                         cudaFuncAttributeMaxDynamicSharedMemorySize, DYN_SMEM);

    wsplit_kernel<<<64, 256>>>(Wg, Wn);
    dim3 grid(T_TOK / CTA_M, 2);
    router_gemm_mma<<<grid, 256, DYN_SMEM>>>(H);
    router_topk_kernel<<<(T_TOK * 32) / 256, 256>>>(noise, out);
    dummy_kernel<<<1, 1>>>();
}

// round 11
// speedup vs baseline: 1.3719x; 1.3719x over previous
#include <cuda_runtime.h>
#include <cuda_fp16.h>
#include <math.h>
#include <cstdint>

#define T_TOK   16384
#define DIM     2048
#define N_EXP   64
#define NC      128
#define TOPK    8

#define CTA_M   128
#define CTA_N   64
#define KT      32
#define NTILE   (DIM / KT)      // 64
#define PITCH   40              // halves per row: 80B, 16B-aligned, frag-conflict-free
#define ABUF    (CTA_M * PITCH) // halves per A array stage
#define BBUF    (CTA_N * PITCH)
// smem halves: As0,As1 (2 stages each) + Bs0,Bs1 (2 stages each)
#define SM_HALVES (4 * ABUF + 4 * BBUF)
#define DYN_SMEM  (SM_HALVES * 2)    // 61440 B

#define CLO     0.0009765625f   // 2^-10, cross-term scale

__device__ float  g_logits[(size_t)T_TOK * NC];
__device__ __half g_W0[(size_t)NC * DIM];   // fp16(w)
__device__ __half g_W1[(size_t)NC * DIM];   // fp16((w - w0) * 1024)

__device__ __forceinline__ void mma16(float c[4], const uint32_t a[4], const uint32_t b[2]) {
    asm volatile(
        "mma.sync.aligned.m16n8k16.row.col.f32.f16.f16.f32 "
        "{%0,%1,%2,%3}, {%4,%5,%6,%7}, {%8,%9}, {%0,%1,%2,%3};"
        : "+f"(c[0]), "+f"(c[1]), "+f"(c[2]), "+f"(c[3])
        : "r"(a[0]), "r"(a[1]), "r"(a[2]), "r"(a[3]), "r"(b[0]), "r"(b[1]));
}

// ---------------------------------------------------------------------------
// Kernel 0: split W = [Wg; Wn] into fp16 hi + scaled-lo (x1024, normal range)
// ---------------------------------------------------------------------------
__global__ void wsplit_kernel(const float* __restrict__ Wg,
                              const float* __restrict__ Wn) {
    const int i0 = (blockIdx.x * 256 + threadIdx.x) * 16;
#pragma unroll
    for (int f = 0; f < 8; f++) {
        const int i = i0 + f * 2;
        float2 w = (i < N_EXP * DIM)
                 ? *(const float2*)(Wg + i)
                 : *(const float2*)(Wn + (i - N_EXP * DIM));
        __half2 h0 = __floats2half2_rn(w.x, w.y);
        float2  b0 = __half22float2(h0);
        __half2 h1 = __floats2half2_rn((w.x - b0.x) * 1024.f,
                                       (w.y - b0.y) * 1024.f);
        *(__half2*)(g_W0 + i) = h0;
        *(__half2*)(g_W1 + i) = h1;
    }
}

// ---------------------------------------------------------------------------
// Kernel 1: logits = H @ [Wg;Wn]^T via fp16 m16n8k16 3-term split.
//   acc_a = h0*w0 ; acc_c = h0*w1' + h1'*w0  (both scaled 2^10 on the lo side)
//   every 2 tiles (64 k): acc2 += acc_a + acc_c * 2^-10  (RN cascade, kills
//   tensor-core RZ bias — same structure that passed in R8)
// R8-proven skeleton: register staging, double smem buffer, 1 sync/tile.
// ---------------------------------------------------------------------------
__global__ void __launch_bounds__(256)
router_gemm_f16(const float* __restrict__ H) {
    extern __shared__ __half smh[];
    __half* As0 = smh;                  // [2][CTA_M][PITCH]
    __half* As1 = As0 + 2 * ABUF;
    __half* Bs0 = As1 + 2 * ABUF;       // [2][CTA_N][PITCH]
    __half* Bs1 = Bs0 + 2 * BBUF;

    const int tid  = threadIdx.x;
    const int lane = tid & 31;
    const int wid  = tid >> 5;
    const int wm   = wid & 3;           // 32-row group
    const int wn   = wid >> 2;          // 32-col group
    const int m0   = blockIdx.x * CTA_M;
    const int fr   = lane >> 2;
    const int fc   = lane & 3;

    // loaders: A fp32->split; B preloaded fp16
    const int a_row = tid >> 1, a_kh = (tid & 1) * 16;    // 16 floats/thread
    const int b_row = tid >> 2, b_kh = (tid & 3) * 8;     // 8 halves/array/thread
    const float* aG  = H + (size_t)(m0 + a_row) * DIM;
    const __half* b0G = g_W0 + (size_t)(blockIdx.y * CTA_N + b_row) * DIM;
    const __half* b1G = g_W1 + (size_t)(blockIdx.y * CTA_N + b_row) * DIM;

    float acc_a[2][4][4], acc_c[2][4][4], acc2[2][4][4];
#pragma unroll
    for (int i = 0; i < 2; i++)
#pragma unroll
        for (int j = 0; j < 4; j++)
#pragma unroll
            for (int r = 0; r < 4; r++) {
                acc_a[i][j][r] = 0.f; acc_c[i][j][r] = 0.f; acc2[i][j][r] = 0.f;
            }

    // register prefetch of tile 0
    float4 av[4];
    uint4  bv0, bv1;
#pragma unroll
    for (int f = 0; f < 4; f++) av[f] = *(const float4*)(aG + a_kh + f * 4);
    bv0 = *(const uint4*)(b0G + b_kh);
    bv1 = *(const uint4*)(b1G + b_kh);

    // split + store helper (A): 16 floats -> 8 half2 per array
    auto store_a = [&](int stage) {
        __half* d0 = As0 + stage * ABUF + a_row * PITCH + a_kh;
        __half* d1 = As1 + stage * ABUF + a_row * PITCH + a_kh;
#pragma unroll
        for (int f = 0; f < 4; f++) {
            float fx = av[f].x, fy = av[f].y, fz = av[f].z, fw = av[f].w;
            __half2 p0 = __floats2half2_rn(fx, fy);
            __half2 p1 = __floats2half2_rn(fz, fw);
            float2 c0 = __half22float2(p0), c1 = __half22float2(p1);
            __half2 q0 = __floats2half2_rn((fx - c0.x) * 1024.f, (fy - c0.y) * 1024.f);
            __half2 q1 = __floats2half2_rn((fz - c1.x) * 1024.f, (fw - c1.y) * 1024.f);
            *(__half2*)(d0 + f * 4)     = p0;
            *(__half2*)(d0 + f * 4 + 2) = p1;
            *(__half2*)(d1 + f * 4)     = q0;
            *(__half2*)(d1 + f * 4 + 2) = q1;
        }
    };
    auto store_b = [&](int stage) {
        *(uint4*)(Bs0 + stage * BBUF + b_row * PITCH + b_kh) = bv0;
        *(uint4*)(Bs1 + stage * BBUF + b_row * PITCH + b_kh) = bv1;
    };

    store_a(0); store_b(0);
    __syncthreads();

    for (int t = 0; t < NTILE; t++) {
        const int s = t & 1;
        const bool more = (t + 1 < NTILE);
        if (more) {   // global prefetch during compute
            const int kb = (t + 1) * KT;
#pragma unroll
            for (int f = 0; f < 4; f++) av[f] = *(const float4*)(aG + kb + a_kh + f * 4);
            bv0 = *(const uint4*)(b0G + kb + b_kh);
            bv1 = *(const uint4*)(b1G + kb + b_kh);
        }

        const __half* A0 = As0 + s * ABUF;
        const __half* A1 = As1 + s * ABUF;
        const __half* B0 = Bs0 + s * BBUF;
        const __half* B1 = Bs1 + s * BBUF;

#pragma unroll
        for (int ks = 0; ks < 2; ks++) {        // two k16 steps per 32-k tile
            const int kc = ks * 16 + 2 * fc;
            uint32_t a0f[2][4], a1f[2][4];
#pragma unroll
            for (int mt = 0; mt < 2; mt++) {
                const int r0 = (wm * 32 + mt * 16 + fr) * PITCH;
                const int r8 = r0 + 8 * PITCH;
                a0f[mt][0] = *(const uint32_t*)(A0 + r0 + kc);
                a0f[mt][1] = *(const uint32_t*)(A0 + r8 + kc);
                a0f[mt][2] = *(const uint32_t*)(A0 + r0 + kc + 8);
                a0f[mt][3] = *(const uint32_t*)(A0 + r8 + kc + 8);
                a1f[mt][0] = *(const uint32_t*)(A1 + r0 + kc);
                a1f[mt][1] = *(const uint32_t*)(A1 + r8 + kc);
                a1f[mt][2] = *(const uint32_t*)(A1 + r0 + kc + 8);
                a1f[mt][3] = *(const uint32_t*)(A1 + r8 + kc + 8);
            }
            uint32_t b0f[4][2], b1f[4][2];
#pragma unroll
            for (int nt = 0; nt < 4; nt++) {
                const int nr = (wn * 32 + nt * 8 + fr) * PITCH;
                b0f[nt][0] = *(const uint32_t*)(B0 + nr + kc);
                b0f[nt][1] = *(const uint32_t*)(B0 + nr + kc + 8);
                b1f[nt][0] = *(const uint32_t*)(B1 + nr + kc);
                b1f[nt][1] = *(const uint32_t*)(B1 + nr + kc + 8);
            }
#pragma unroll
            for (int mt = 0; mt < 2; mt++)
#pragma unroll
                for (int nt = 0; nt < 4; nt++) mma16(acc_a[mt][nt], a0f[mt], b0f[nt]);
#pragma unroll
            for (int mt = 0; mt < 2; mt++)
#pragma unroll
                for (int nt = 0; nt < 4; nt++) mma16(acc_c[mt][nt], a0f[mt], b1f[nt]);
#pragma unroll
            for (int mt = 0; mt < 2; mt++)
#pragma unroll
                for (int nt = 0; nt < 4; nt++) mma16(acc_c[mt][nt], a1f[mt], b0f[nt]);
        }

        if (more) { store_a(s ^ 1); store_b(s ^ 1); }
        __syncthreads();

        if ((t & 1) == 1) {   // 64-k cascade, RN adds (RZ-bias mitigation)
#pragma unroll
            for (int mt = 0; mt < 2; mt++)
#pragma unroll
                for (int nt = 0; nt < 4; nt++)
#pragma unroll
                    for (int r = 0; r < 4; r++) {
                        acc2[mt][nt][r] += acc_a[mt][nt][r] + acc_c[mt][nt][r] * CLO;
                        acc_a[mt][nt][r] = 0.f;
                        acc_c[mt][nt][r] = 0.f;
                    }
        }
    }

    // epilogue
#pragma unroll
    for (int mt = 0; mt < 2; mt++)
#pragma unroll
        for (int nt = 0; nt < 4; nt++) {
            const int row = m0 + wm * 32 + mt * 16 + fr;
            const int col = blockIdx.y * CTA_N + wn * 32 + nt * 8 + fc * 2;
            *(float2*)&g_logits[(size_t)row * NC + col] =
                make_float2(acc2[mt][nt][0], acc2[mt][nt][1]);
            *(float2*)&g_logits[(size_t)(row + 8) * NC + col] =
                make_float2(acc2[mt][nt][2], acc2[mt][nt][3]);
        }
}

// ---------------------------------------------------------------------------
// Kernel 2: one warp per token — noisy logits, softmax(64), top-8 desc
// ---------------------------------------------------------------------------
__device__ __forceinline__ float softplus_f(float x) {
    return fmaxf(x, 0.0f) + log1pf(expf(-fabsf(x)));
}

__global__ void __launch_bounds__(256)
router_topk_kernel(const float* __restrict__ noise, float* __restrict__ out) {
    const int warp = (blockIdx.x * blockDim.x + threadIdx.x) >> 5;
    const int lane = threadIdx.x & 31;
    if (warp >= T_TOK) return;

    const float* row = g_logits + (size_t)warp * NC;
    const float* nz  = noise + (size_t)warp * N_EXP;

    float g0 = row[lane]      + nz[lane]      * softplus_f(row[64 + lane]);
    float g1 = row[lane + 32] + nz[lane + 32] * softplus_f(row[96 + lane]);

    float mx = fmaxf(g0, g1);
#pragma unroll
    for (int o = 16; o > 0; o >>= 1) mx = fmaxf(mx, __shfl_xor_sync(0xffffffffu, mx, o));
    float e0 = expf(g0 - mx), e1 = expf(g1 - mx);
    float s = e0 + e1;
#pragma unroll
    for (int o = 16; o > 0; o >>= 1) s += __shfl_xor_sync(0xffffffffu, s, o);
    const float inv = 1.0f / s;
    float p0 = e0 * inv, p1 = e1 * inv;

    float* gates = out + (size_t)2 * T_TOK * TOPK + (size_t)warp * N_EXP;
    gates[lane]      = p0;
    gates[lane + 32] = p1;

    float v0 = p0, v1 = p1;
    float* vals = out + (size_t)warp * TOPK;
    float* inds = out + (size_t)T_TOK * TOPK + (size_t)warp * TOPK;

#pragma unroll
    for (int r = 0; r < TOPK; r++) {
        float cv; int ci;
        if (v0 >= v1) { cv = v0; ci = lane; }
        else          { cv = v1; ci = lane + 32; }
#pragma unroll
        for (int o = 16; o > 0; o >>= 1) {
            float ov = __shfl_xor_sync(0xffffffffu, cv, o);
            int   oi = __shfl_xor_sync(0xffffffffu, ci, o);
            if (ov > cv || (ov == cv && oi < ci)) { cv = ov; ci = oi; }
        }
        if (lane == 0) { vals[r] = cv; inds[r] = (float)ci; }
        if (ci == lane)      v0 = -INFINITY;
        if (ci == lane + 32) v1 = -INFINITY;
    }
}

// ---------------------------------------------------------------------------
extern "C" void kernel_launch(void* const* d_in, const int* in_sizes, int n_in,
                              void* d_out, int out_size) {
    const float* H     = (const float*)d_in[0];
    const float* Wg    = (const float*)d_in[1];
    const float* Wn    = (const float*)d_in[2];
    const float* noise = (const float*)d_in[3];
    float* out = (float*)d_out;

    cudaFuncSetAttribute(router_gemm_f16,
                         cudaFuncAttributeMaxDynamicSharedMemorySize, DYN_SMEM);

    wsplit_kernel<<<64, 256>>>(Wg, Wn);
    dim3 grid(T_TOK / CTA_M, 2);
    router_gemm_f16<<<grid, 256, DYN_SMEM>>>(H);
    router_topk_kernel<<<(T_TOK * 32) / 256, 256>>>(noise, out);
}

// round 12
// speedup vs baseline: 1.5189x; 1.1071x over previous
#include <cuda_runtime.h>
#include <cuda_fp16.h>
#include <math.h>
#include <cstdint>

#define T_TOK   16384
#define DIM     2048
#define N_EXP   64
#define NC      128
#define TOPK    8

#define CTA_M   128
#define CTA_N   64
#define KT      32
#define NTILE   (DIM / KT)      // 64
#define PITCH   40              // halves per row: 80B, 16B-aligned, conflict-free
#define ABUF    (CTA_M * PITCH) // halves per A array stage
#define BBUF    (CTA_N * PITCH)
// halves: As0,As1,Bs0,Bs1 (2 stages each) ; + acc2 floats [32][256]
#define SM_HALVES (4 * ABUF + 4 * BBUF)
#define DYN_SMEM  (SM_HALVES * 2 + 32 * 256 * 4)    // 61440 + 32768 = 94208 B

#define CLO     0.0009765625f   // 2^-10, cross-term scale

__device__ float  g_logits[(size_t)T_TOK * NC];
__device__ __half g_W0[(size_t)NC * DIM];   // fp16(w)
__device__ __half g_W1[(size_t)NC * DIM];   // fp16((w - w0) * 1024)

__device__ __forceinline__ void mma16(float c[4], const uint32_t a[4], const uint32_t b[2]) {
    asm volatile(
        "mma.sync.aligned.m16n8k16.row.col.f32.f16.f16.f32 "
        "{%0,%1,%2,%3}, {%4,%5,%6,%7}, {%8,%9}, {%0,%1,%2,%3};"
        : "+f"(c[0]), "+f"(c[1]), "+f"(c[2]), "+f"(c[3])
        : "r"(a[0]), "r"(a[1]), "r"(a[2]), "r"(a[3]), "r"(b[0]), "r"(b[1]));
}

// ---------------------------------------------------------------------------
// Kernel 0: split W = [Wg; Wn] into fp16 hi + scaled-lo (x1024, normal range)
// ---------------------------------------------------------------------------
__global__ void wsplit_kernel(const float* __restrict__ Wg,
                              const float* __restrict__ Wn) {
    const int i0 = (blockIdx.x * 256 + threadIdx.x) * 16;
#pragma unroll
    for (int f = 0; f < 8; f++) {
        const int i = i0 + f * 2;
        float2 w = (i < N_EXP * DIM)
                 ? *(const float2*)(Wg + i)
                 : *(const float2*)(Wn + (i - N_EXP * DIM));
        __half2 h0 = __floats2half2_rn(w.x, w.y);
        float2  b0 = __half22float2(h0);
        __half2 h1 = __floats2half2_rn((w.x - b0.x) * 1024.f,
                                       (w.y - b0.y) * 1024.f);
        *(__half2*)(g_W0 + i) = h0;
        *(__half2*)(g_W1 + i) = h1;
    }
}

// ---------------------------------------------------------------------------
// Kernel 1: logits = H @ [Wg;Wn]^T via fp16 m16n8k16 3-term split.
// Numerics bitwise identical to R11 (same MMA set/order, same 64k RN cascade
// acc2 += acc_a + acc_c*CLO). Scheduling: occ 2 via acc2-in-smem (-32 regs)
// and term-sequenced frag loads (-16 regs), __launch_bounds__(256,2).
// ---------------------------------------------------------------------------
__global__ void __launch_bounds__(256, 2)
router_gemm_f16(const float* __restrict__ H) {
    extern __shared__ __half smh[];
    __half* As0 = smh;                  // [2][CTA_M][PITCH]
    __half* As1 = As0 + 2 * ABUF;
    __half* Bs0 = As1 + 2 * ABUF;       // [2][CTA_N][PITCH]
    __half* Bs1 = Bs0 + 2 * BBUF;
    float*  acc2s = (float*)(Bs1 + 2 * BBUF);   // [32][256]

    const int tid  = threadIdx.x;
    const int lane = tid & 31;
    const int wid  = tid >> 5;
    const int wm   = wid & 3;           // 32-row group
    const int wn   = wid >> 2;          // 32-col group
    const int m0   = blockIdx.x * CTA_M;
    const int fr   = lane >> 2;
    const int fc   = lane & 3;

    // loaders: A fp32->split; B preloaded fp16
    const int a_row = tid >> 1, a_kh = (tid & 1) * 16;    // 16 floats/thread
    const int b_row = tid >> 2, b_kh = (tid & 3) * 8;     // 8 halves/array/thread
    const float* aG  = H + (size_t)(m0 + a_row) * DIM;
    const __half* b0G = g_W0 + (size_t)(blockIdx.y * CTA_N + b_row) * DIM;
    const __half* b1G = g_W1 + (size_t)(blockIdx.y * CTA_N + b_row) * DIM;

    float acc_a[2][4][4], acc_c[2][4][4];
#pragma unroll
    for (int i = 0; i < 2; i++)
#pragma unroll
        for (int j = 0; j < 4; j++)
#pragma unroll
            for (int r = 0; r < 4; r++) { acc_a[i][j][r] = 0.f; acc_c[i][j][r] = 0.f; }
#pragma unroll
    for (int r = 0; r < 32; r++) acc2s[r * 256 + tid] = 0.f;

    // register prefetch of tile 0
    float4 av[4];
    uint4  bv0, bv1;
#pragma unroll
    for (int f = 0; f < 4; f++) av[f] = *(const float4*)(aG + a_kh + f * 4);
    bv0 = *(const uint4*)(b0G + b_kh);
    bv1 = *(const uint4*)(b1G + b_kh);

    auto store_a = [&](int stage) {
        __half* d0 = As0 + stage * ABUF + a_row * PITCH + a_kh;
        __half* d1 = As1 + stage * ABUF + a_row * PITCH + a_kh;
#pragma unroll
        for (int f = 0; f < 4; f++) {
            float fx = av[f].x, fy = av[f].y, fz = av[f].z, fw = av[f].w;
            __half2 p0 = __floats2half2_rn(fx, fy);
            __half2 p1 = __floats2half2_rn(fz, fw);
            float2 c0 = __half22float2(p0), c1 = __half22float2(p1);
            __half2 q0 = __floats2half2_rn((fx - c0.x) * 1024.f, (fy - c0.y) * 1024.f);
            __half2 q1 = __floats2half2_rn((fz - c1.x) * 1024.f, (fw - c1.y) * 1024.f);
            *(__half2*)(d0 + f * 4)     = p0;
            *(__half2*)(d0 + f * 4 + 2) = p1;
            *(__half2*)(d1 + f * 4)     = q0;
            *(__half2*)(d1 + f * 4 + 2) = q1;
        }
    };
    auto store_b = [&](int stage) {
        *(uint4*)(Bs0 + stage * BBUF + b_row * PITCH + b_kh) = bv0;
        *(uint4*)(Bs1 + stage * BBUF + b_row * PITCH + b_kh) = bv1;
    };

    store_a(0); store_b(0);
    __syncthreads();

    for (int t = 0; t < NTILE; t++) {
        const int s = t & 1;
        const bool more = (t + 1 < NTILE);
        if (more) {   // global prefetch during compute
            const int kb = (t + 1) * KT;
#pragma unroll
            for (int f = 0; f < 4; f++) av[f] = *(const float4*)(aG + kb + a_kh + f * 4);
            bv0 = *(const uint4*)(b0G + kb + b_kh);
            bv1 = *(const uint4*)(b1G + kb + b_kh);
        }

        const __half* A0 = As0 + s * ABUF;
        const __half* A1 = As1 + s * ABUF;
        const __half* B0 = Bs0 + s * BBUF;
        const __half* B1 = Bs1 + s * BBUF;

#pragma unroll
        for (int ks = 0; ks < 2; ks++) {
            const int kc = ks * 16 + 2 * fc;
            uint32_t af[2][4], b0f[4][2], b1f[4][2];
            // A0 frags
#pragma unroll
            for (int mt = 0; mt < 2; mt++) {
                const int r0 = (wm * 32 + mt * 16 + fr) * PITCH;
                const int r8 = r0 + 8 * PITCH;
                af[mt][0] = *(const uint32_t*)(A0 + r0 + kc);
                af[mt][1] = *(const uint32_t*)(A0 + r8 + kc);
                af[mt][2] = *(const uint32_t*)(A0 + r0 + kc + 8);
                af[mt][3] = *(const uint32_t*)(A0 + r8 + kc + 8);
            }
#pragma unroll
            for (int nt = 0; nt < 4; nt++) {
                const int nr = (wn * 32 + nt * 8 + fr) * PITCH;
                b0f[nt][0] = *(const uint32_t*)(B0 + nr + kc);
                b0f[nt][1] = *(const uint32_t*)(B0 + nr + kc + 8);
            }
#pragma unroll
            for (int mt = 0; mt < 2; mt++)
#pragma unroll
                for (int nt = 0; nt < 4; nt++) mma16(acc_a[mt][nt], af[mt], b0f[nt]);
            // B1 frags -> acc_c += a0*b1
#pragma unroll
            for (int nt = 0; nt < 4; nt++) {
                const int nr = (wn * 32 + nt * 8 + fr) * PITCH;
                b1f[nt][0] = *(const uint32_t*)(B1 + nr + kc);
                b1f[nt][1] = *(const uint32_t*)(B1 + nr + kc + 8);
            }
#pragma unroll
            for (int mt = 0; mt < 2; mt++)
#pragma unroll
                for (int nt = 0; nt < 4; nt++) mma16(acc_c[mt][nt], af[mt], b1f[nt]);
            // A1 frags reuse af -> acc_c += a1*b0
#pragma unroll
            for (int mt = 0; mt < 2; mt++) {
                const int r0 = (wm * 32 + mt * 16 + fr) * PITCH;
                const int r8 = r0 + 8 * PITCH;
                af[mt][0] = *(const uint32_t*)(A1 + r0 + kc);
                af[mt][1] = *(const uint32_t*)(A1 + r8 + kc);
                af[mt][2] = *(const uint32_t*)(A1 + r0 + kc + 8);
                af[mt][3] = *(const uint32_t*)(A1 + r8 + kc + 8);
            }
#pragma unroll
            for (int mt = 0; mt < 2; mt++)
#pragma unroll
                for (int nt = 0; nt < 4; nt++) mma16(acc_c[mt][nt], af[mt], b0f[nt]);
        }

        if (more) { store_a(s ^ 1); store_b(s ^ 1); }
        __syncthreads();

        if ((t & 1) == 1) {   // 64-k cascade, RN adds (same expression as R11)
#pragma unroll
            for (int mt = 0; mt < 2; mt++)
#pragma unroll
                for (int nt = 0; nt < 4; nt++)
#pragma unroll
                    for (int r = 0; r < 4; r++) {
                        const int idx = (mt * 4 + nt) * 4 + r;
                        acc2s[idx * 256 + tid] += acc_a[mt][nt][r] + acc_c[mt][nt][r] * CLO;
                        acc_a[mt][nt][r] = 0.f;
                        acc_c[mt][nt][r] = 0.f;
                    }
        }
    }

    // epilogue
#pragma unroll
    for (int mt = 0; mt < 2; mt++)
#pragma unroll
        for (int nt = 0; nt < 4; nt++) {
            const int row = m0 + wm * 32 + mt * 16 + fr;
            const int col = blockIdx.y * CTA_N + wn * 32 + nt * 8 + fc * 2;
            const int idx = (mt * 4 + nt) * 4;
            float v0 = acc2s[(idx + 0) * 256 + tid];
            float v1 = acc2s[(idx + 1) * 256 + tid];
            float v2 = acc2s[(idx + 2) * 256 + tid];
            float v3 = acc2s[(idx + 3) * 256 + tid];
            *(float2*)&g_logits[(size_t)row * NC + col]       = make_float2(v0, v1);
            *(float2*)&g_logits[(size_t)(row + 8) * NC + col] = make_float2(v2, v3);
        }
}

// ---------------------------------------------------------------------------
// Kernel 2: one warp per token — noisy logits, softmax(64), top-8 desc
// ---------------------------------------------------------------------------
__device__ __forceinline__ float softplus_f(float x) {
    return fmaxf(x, 0.0f) + log1pf(expf(-fabsf(x)));
}

__global__ void __launch_bounds__(256)
router_topk_kernel(const float* __restrict__ noise, float* __restrict__ out) {
    const int warp = (blockIdx.x * blockDim.x + threadIdx.x) >> 5;
    const int lane = threadIdx.x & 31;
    if (warp >= T_TOK) return;

    const float* row = g_logits + (size_t)warp * NC;
    const float* nz  = noise + (size_t)warp * N_EXP;

    float g0 = row[lane]      + nz[lane]      * softplus_f(row[64 + lane]);
    float g1 = row[lane + 32] + nz[lane + 32] * softplus_f(row[96 + lane]);

    float mx = fmaxf(g0, g1);
#pragma unroll
    for (int o = 16; o > 0; o >>= 1) mx = fmaxf(mx, __shfl_xor_sync(0xffffffffu, mx, o));
    float e0 = expf(g0 - mx), e1 = expf(g1 - mx);
    float s = e0 + e1;
#pragma unroll
    for (int o = 16; o > 0; o >>= 1) s += __shfl_xor_sync(0xffffffffu, s, o);
    const float inv = 1.0f / s;
    float p0 = e0 * inv, p1 = e1 * inv;

    float* gates = out + (size_t)2 * T_TOK * TOPK + (size_t)warp * N_EXP;
    gates[lane]      = p0;
    gates[lane + 32] = p1;

    float v0 = p0, v1 = p1;
    float* vals = out + (size_t)warp * TOPK;
    float* inds = out + (size_t)T_TOK * TOPK + (size_t)warp * TOPK;

#pragma unroll
    for (int r = 0; r < TOPK; r++) {
        float cv; int ci;
        if (v0 >= v1) { cv = v0; ci = lane; }
        else          { cv = v1; ci = lane + 32; }
#pragma unroll
        for (int o = 16; o > 0; o >>= 1) {
            float ov = __shfl_xor_sync(0xffffffffu, cv, o);
            int   oi = __shfl_xor_sync(0xffffffffu, ci, o);
            if (ov > cv || (ov == cv && oi < ci)) { cv = ov; ci = oi; }
        }
        if (lane == 0) { vals[r] = cv; inds[r] = (float)ci; }
        if (ci == lane)      v0 = -INFINITY;
        if (ci == lane + 32) v1 = -INFINITY;
    }
}

// ---------------------------------------------------------------------------
extern "C" void kernel_launch(void* const* d_in, const int* in_sizes, int n_in,
                              void* d_out, int out_size) {
    const float* H     = (const float*)d_in[0];
    const float* Wg    = (const float*)d_in[1];
    const float* Wn    = (const float*)d_in[2];
    const float* noise = (const float*)d_in[3];
    float* out = (float*)d_out;

    cudaFuncSetAttribute(router_gemm_f16,
                         cudaFuncAttributeMaxDynamicSharedMemorySize, DYN_SMEM);

    wsplit_kernel<<<64, 256>>>(Wg, Wn);
    dim3 grid(T_TOK / CTA_M, 2);
    router_gemm_f16<<<grid, 256, DYN_SMEM>>>(H);
    router_topk_kernel<<<(T_TOK * 32) / 256, 256>>>(noise, out);
}

// round 13
// speedup vs baseline: 1.6487x; 1.0855x over previous
#include <cuda_runtime.h>
#include <cuda_fp16.h>
#include <math.h>
#include <cstdint>

#define T_TOK   16384
#define DIM     2048
#define N_EXP   64
#define NC      128
#define TOPK    8

#define CTA_M   128
#define CTA_N   64
#define KT      32
#define NTILE   (DIM / KT)      // 64
#define PITCH   40              // halves per row: 80B, LDSM-conflict-free
#define ABUF    (CTA_M * PITCH)
#define BBUF    (CTA_N * PITCH)
#define SM_HALVES (4 * ABUF + 4 * BBUF)
#define DYN_SMEM  (SM_HALVES * 2 + 32 * 256 * 4)    // 94208 B

#define CLO     0.0009765625f   // 2^-10 cross-term scale

__device__ float  g_logits[(size_t)T_TOK * NC];
__device__ __half g_W0[(size_t)NC * DIM];
__device__ __half g_W1[(size_t)NC * DIM];

__device__ __forceinline__ void mma16(float c[4], const uint32_t a[4], const uint32_t b[2]) {
    asm volatile(
        "mma.sync.aligned.m16n8k16.row.col.f32.f16.f16.f32 "
        "{%0,%1,%2,%3}, {%4,%5,%6,%7}, {%8,%9}, {%0,%1,%2,%3};"
        : "+f"(c[0]), "+f"(c[1]), "+f"(c[2]), "+f"(c[3])
        : "r"(a[0]), "r"(a[1]), "r"(a[2]), "r"(a[3]), "r"(b[0]), "r"(b[1]));
}
__device__ __forceinline__ uint32_t smem_u32(const void* p) {
    uint32_t a;
    asm("{ .reg .u64 t; cvta.to.shared.u64 t, %1; cvt.u32.u64 %0, t; }"
        : "=r"(a) : "l"(p));
    return a;
}
__device__ __forceinline__ void ldsm4(uint32_t r[4], uint32_t addr) {
    asm volatile("ldmatrix.sync.aligned.m8n8.x4.shared.b16 {%0,%1,%2,%3}, [%4];"
                 : "=r"(r[0]), "=r"(r[1]), "=r"(r[2]), "=r"(r[3]) : "r"(addr));
}

// ---------------------------------------------------------------------------
// Kernel 0: split W into fp16 hi + scaled-lo (x1024); 256 blocks (latency)
// ---------------------------------------------------------------------------
__global__ void wsplit_kernel(const float* __restrict__ Wg,
                              const float* __restrict__ Wn) {
    const int i0 = (blockIdx.x * 256 + threadIdx.x) * 4;
#pragma unroll
    for (int f = 0; f < 2; f++) {
        const int i = i0 + f * 2;
        float2 w = (i < N_EXP * DIM)
                 ? *(const float2*)(Wg + i)
                 : *(const float2*)(Wn + (i - N_EXP * DIM));
        __half2 h0 = __floats2half2_rn(w.x, w.y);
        float2  b0 = __half22float2(h0);
        __half2 h1 = __floats2half2_rn((w.x - b0.x) * 1024.f,
                                       (w.y - b0.y) * 1024.f);
        *(__half2*)(g_W0 + i) = h0;
        *(__half2*)(g_W1 + i) = h1;
    }
}

// ---------------------------------------------------------------------------
// Kernel 1: fp16 m16n8k16 3-term split GEMM (numerics bitwise = R12).
// Change: all fragment loads via ldmatrix.x4 (16 LDSM/tile vs 64 LDS).
// ---------------------------------------------------------------------------
__global__ void __launch_bounds__(256, 2)
router_gemm_f16(const float* __restrict__ H) {
    extern __shared__ __half smh[];
    __half* As0 = smh;                  // [2][CTA_M][PITCH]
    __half* As1 = As0 + 2 * ABUF;
    __half* Bs0 = As1 + 2 * ABUF;       // [2][CTA_N][PITCH]
    __half* Bs1 = Bs0 + 2 * BBUF;
    float*  acc2s = (float*)(Bs1 + 2 * BBUF);   // [32][256]

    const int tid  = threadIdx.x;
    const int lane = tid & 31;
    const int wid  = tid >> 5;
    const int wm   = wid & 3;
    const int wn   = wid >> 2;
    const int m0   = blockIdx.x * CTA_M;
    const int fr   = lane >> 2;
    const int fc   = lane & 3;

    // ldmatrix per-lane geometry (halves offsets)
    // A x4: m0=(r0,k0) m1=(r8,k0) m2=(r0,k8) m3=(r8,k8)
    const int a_lm_row = (lane & 7) + ((lane >> 3) & 1) * 8;
    const int a_lm_k   = (lane >> 4) * 8;
    // B x4 (nt-pair): m0=(nt,k0) m1=(nt,k8) m2=(nt+1,k0) m3=(nt+1,k8)
    const int b_lm_row = (lane & 7) + (lane >> 4) * 8;
    const int b_lm_k   = ((lane >> 3) & 1) * 8;

    const uint32_t uA0 = smem_u32(As0), uA1 = smem_u32(As1);
    const uint32_t uB0 = smem_u32(Bs0), uB1 = smem_u32(Bs1);
    // base offsets in bytes (half = 2B)
    const uint32_t aoff = (uint32_t)(((wm * 32 + a_lm_row) * PITCH + a_lm_k) * 2);
    const uint32_t boff = (uint32_t)(((wn * 32 + b_lm_row) * PITCH + b_lm_k) * 2);

    // loaders
    const int a_row = tid >> 1, a_kh = (tid & 1) * 16;
    const int b_row = tid >> 2, b_kh = (tid & 3) * 8;
    const float* aG  = H + (size_t)(m0 + a_row) * DIM;
    const __half* b0G = g_W0 + (size_t)(blockIdx.y * CTA_N + b_row) * DIM;
    const __half* b1G = g_W1 + (size_t)(blockIdx.y * CTA_N + b_row) * DIM;

    float acc_a[2][4][4], acc_c[2][4][4];
#pragma unroll
    for (int i = 0; i < 2; i++)
#pragma unroll
        for (int j = 0; j < 4; j++)
#pragma unroll
            for (int r = 0; r < 4; r++) { acc_a[i][j][r] = 0.f; acc_c[i][j][r] = 0.f; }
#pragma unroll
    for (int r = 0; r < 32; r++) acc2s[r * 256 + tid] = 0.f;

    float4 av[4];
    uint4  bv0, bv1;
#pragma unroll
    for (int f = 0; f < 4; f++) av[f] = *(const float4*)(aG + a_kh + f * 4);
    bv0 = *(const uint4*)(b0G + b_kh);
    bv1 = *(const uint4*)(b1G + b_kh);

    auto store_a = [&](int stage) {
        __half* d0 = As0 + stage * ABUF + a_row * PITCH + a_kh;
        __half* d1 = As1 + stage * ABUF + a_row * PITCH + a_kh;
#pragma unroll
        for (int f = 0; f < 4; f++) {
            float fx = av[f].x, fy = av[f].y, fz = av[f].z, fw = av[f].w;
            __half2 p0 = __floats2half2_rn(fx, fy);
            __half2 p1 = __floats2half2_rn(fz, fw);
            float2 c0 = __half22float2(p0), c1 = __half22float2(p1);
            __half2 q0 = __floats2half2_rn((fx - c0.x) * 1024.f, (fy - c0.y) * 1024.f);
            __half2 q1 = __floats2half2_rn((fz - c1.x) * 1024.f, (fw - c1.y) * 1024.f);
            *(__half2*)(d0 + f * 4)     = p0;
            *(__half2*)(d0 + f * 4 + 2) = p1;
            *(__half2*)(d1 + f * 4)     = q0;
            *(__half2*)(d1 + f * 4 + 2) = q1;
        }
    };
    auto store_b = [&](int stage) {
        *(uint4*)(Bs0 + stage * BBUF + b_row * PITCH + b_kh) = bv0;
        *(uint4*)(Bs1 + stage * BBUF + b_row * PITCH + b_kh) = bv1;
    };

    store_a(0); store_b(0);
    __syncthreads();

    for (int t = 0; t < NTILE; t++) {
        const int s = t & 1;
        const bool more = (t + 1 < NTILE);
        if (more) {
            const int kb = (t + 1) * KT;
#pragma unroll
            for (int f = 0; f < 4; f++) av[f] = *(const float4*)(aG + kb + a_kh + f * 4);
            bv0 = *(const uint4*)(b0G + kb + b_kh);
            bv1 = *(const uint4*)(b1G + kb + b_kh);
        }

        const uint32_t stA0 = uA0 + (uint32_t)(s * ABUF * 2) + aoff;
        const uint32_t stA1 = uA1 + (uint32_t)(s * ABUF * 2) + aoff;
        const uint32_t stB0 = uB0 + (uint32_t)(s * BBUF * 2) + boff;
        const uint32_t stB1 = uB1 + (uint32_t)(s * BBUF * 2) + boff;

#pragma unroll
        for (int ks = 0; ks < 2; ks++) {
            const uint32_t kb2 = (uint32_t)(ks * 16 * 2);   // bytes
            uint32_t a0f[2][4], b0f[4][2], b1f[4][2], a1f[2][4];
#pragma unroll
            for (int mt = 0; mt < 2; mt++)
                ldsm4(a0f[mt], stA0 + kb2 + (uint32_t)(mt * 16 * PITCH * 2));
            {   // B0: two nt-pairs
                uint32_t q[4];
                ldsm4(q, stB0 + kb2);
                b0f[0][0] = q[0]; b0f[0][1] = q[1]; b0f[1][0] = q[2]; b0f[1][1] = q[3];
                ldsm4(q, stB0 + kb2 + (uint32_t)(16 * PITCH * 2));
                b0f[2][0] = q[0]; b0f[2][1] = q[1]; b0f[3][0] = q[2]; b0f[3][1] = q[3];
            }
#pragma unroll
            for (int mt = 0; mt < 2; mt++)
#pragma unroll
                for (int nt = 0; nt < 4; nt++) mma16(acc_a[mt][nt], a0f[mt], b0f[nt]);
            {   // B1
                uint32_t q[4];
                ldsm4(q, stB1 + kb2);
                b1f[0][0] = q[0]; b1f[0][1] = q[1]; b1f[1][0] = q[2]; b1f[1][1] = q[3];
                ldsm4(q, stB1 + kb2 + (uint32_t)(16 * PITCH * 2));
                b1f[2][0] = q[0]; b1f[2][1] = q[1]; b1f[3][0] = q[2]; b1f[3][1] = q[3];
            }
#pragma unroll
            for (int mt = 0; mt < 2; mt++)
#pragma unroll
                for (int nt = 0; nt < 4; nt++) mma16(acc_c[mt][nt], a0f[mt], b1f[nt]);
#pragma unroll
            for (int mt = 0; mt < 2; mt++)
                ldsm4(a1f[mt], stA1 + kb2 + (uint32_t)(mt * 16 * PITCH * 2));
#pragma unroll
            for (int mt = 0; mt < 2; mt++)
#pragma unroll
                for (int nt = 0; nt < 4; nt++) mma16(acc_c[mt][nt], a1f[mt], b0f[nt]);
        }

        if (more) { store_a(s ^ 1); store_b(s ^ 1); }
        __syncthreads();

        if ((t & 1) == 1) {
#pragma unroll
            for (int mt = 0; mt < 2; mt++)
#pragma unroll
                for (int nt = 0; nt < 4; nt++)
#pragma unroll
                    for (int r = 0; r < 4; r++) {
                        const int idx = (mt * 4 + nt) * 4 + r;
                        acc2s[idx * 256 + tid] += acc_a[mt][nt][r] + acc_c[mt][nt][r] * CLO;
                        acc_a[mt][nt][r] = 0.f;
                        acc_c[mt][nt][r] = 0.f;
                    }
        }
    }

    // epilogue
#pragma unroll
    for (int mt = 0; mt < 2; mt++)
#pragma unroll
        for (int nt = 0; nt < 4; nt++) {
            const int row = m0 + wm * 32 + mt * 16 + fr;
            const int col = blockIdx.y * CTA_N + wn * 32 + nt * 8 + fc * 2;
            const int idx = (mt * 4 + nt) * 4;
            float v0 = acc2s[(idx + 0) * 256 + tid];
            float v1 = acc2s[(idx + 1) * 256 + tid];
            float v2 = acc2s[(idx + 2) * 256 + tid];
            float v3 = acc2s[(idx + 3) * 256 + tid];
            *(float2*)&g_logits[(size_t)row * NC + col]       = make_float2(v0, v1);
            *(float2*)&g_logits[(size_t)(row + 8) * NC + col] = make_float2(v2, v3);
        }
}

// ---------------------------------------------------------------------------
// Kernel 2: one warp per token — noisy logits, softmax(64), top-8 desc
// ---------------------------------------------------------------------------
__device__ __forceinline__ float softplus_f(float x) {
    return fmaxf(x, 0.0f) + log1pf(expf(-fabsf(x)));
}

__global__ void __launch_bounds__(256)
router_topk_kernel(const float* __restrict__ noise, float* __restrict__ out) {
    const int warp = (blockIdx.x * blockDim.x + threadIdx.x) >> 5;
    const int lane = threadIdx.x & 31;
    if (warp >= T_TOK) return;

    const float* row = g_logits + (size_t)warp * NC;
    const float* nz  = noise + (size_t)warp * N_EXP;

    float g0 = row[lane]      + nz[lane]      * softplus_f(row[64 + lane]);
    float g1 = row[lane + 32] + nz[lane + 32] * softplus_f(row[96 + lane]);

    float mx = fmaxf(g0, g1);
#pragma unroll
    for (int o = 16; o > 0; o >>= 1) mx = fmaxf(mx, __shfl_xor_sync(0xffffffffu, mx, o));
    float e0 = expf(g0 - mx), e1 = expf(g1 - mx);
    float s = e0 + e1;
#pragma unroll
    for (int o = 16; o > 0; o >>= 1) s += __shfl_xor_sync(0xffffffffu, s, o);
    const float inv = 1.0f / s;
    float p0 = e0 * inv, p1 = e1 * inv;

    float* gates = out + (size_t)2 * T_TOK * TOPK + (size_t)warp * N_EXP;
    gates[lane]      = p0;
    gates[lane + 32] = p1;

    float v0 = p0, v1 = p1;
    float* vals = out + (size_t)warp * TOPK;
    float* inds = out + (size_t)T_TOK * TOPK + (size_t)warp * TOPK;

#pragma unroll
    for (int r = 0; r < TOPK; r++) {
        float cv; int ci;
        if (v0 >= v1) { cv = v0; ci = lane; }
        else          { cv = v1; ci = lane + 32; }
#pragma unroll
        for (int o = 16; o > 0; o >>= 1) {
            float ov = __shfl_xor_sync(0xffffffffu, cv, o);
            int   oi = __shfl_xor_sync(0xffffffffu, ci, o);
            if (ov > cv || (ov == cv && oi < ci)) { cv = ov; ci = oi; }
        }
        if (lane == 0) { vals[r] = cv; inds[r] = (float)ci; }
        if (ci == lane)      v0 = -INFINITY;
        if (ci == lane + 32) v1 = -INFINITY;
    }
}

// ---------------------------------------------------------------------------
extern "C" void kernel_launch(void* const* d_in, const int* in_sizes, int n_in,
                              void* d_out, int out_size) {
    const float* H     = (const float*)d_in[0];
    const float* Wg    = (const float*)d_in[1];
    const float* Wn    = (const float*)d_in[2];
    const float* noise = (const float*)d_in[3];
    float* out = (float*)d_out;

    cudaFuncSetAttribute(router_gemm_f16,
                         cudaFuncAttributeMaxDynamicSharedMemorySize, DYN_SMEM);

    wsplit_kernel<<<256, 256>>>(Wg, Wn);
    dim3 grid(T_TOK / CTA_M, 2);
    router_gemm_f16<<<grid, 256, DYN_SMEM>>>(H);
    router_topk_kernel<<<(T_TOK * 32) / 256, 256>>>(noise, out);
}